// round 14
// baseline (speedup 1.0000x reference)
#include <cuda_runtime.h>
#include <cstdint>

// Capsule routing. x:[128,2048,8] W:[32,2048,16,8] out:[128,32,16]
// R14: BOTH passes on tensor pipe.
//   pass0: mma.sync tf32 GEMM (R11/R13, verified).
//   pass1: per-n m16n8k8 mma for u_hat (3-mma hi/lo split = fp32-class),
//          softmax entirely in fragment registers (quad shfl folds + tiny e_sh).
// Identity: b_k = (sum_{i<k} v_i) . u_hat  ->  u_hat/b never materialized.

#define BB 128
#define NN 2048
#define DD 8
#define JJ 32
#define PP 16
#define NNT0 64

// pass1_mma: grid 128 = 8 bt x 16 nt; 16 b, 128 n per CTA; 256 thr (8 warps)
#define NC1M  128
#define NNT1M 16
#define WROW  12                        // W_s row stride (floats): conflict-free
#define WBUF_M (512 * WROW)             // 6144 floats per stage
#define XOFF_M (2 * WBUF_M)             // 12288
#define ESH_M  (XOFF_M + NC1M * 128)    // 28672
#define SMEM1M_B ((ESH_M + 16 * 12) * 4)  // 115456 B

// pass0 mma smem: rows padded to 44 floats
#define RS    44
#define AS_F  (128 * RS)
#define BS_F  (256 * RS)
#define BUF_F (AS_F + BS_F)
#define SMEM0_B (2 * BUF_F * 4)         // 135168 B

__device__ __forceinline__ unsigned smem_u32(const void* p) {
    return (unsigned)__cvta_generic_to_shared(p);
}
__device__ __forceinline__ void cp16(unsigned dst, const void* src) {
    asm volatile("cp.async.cg.shared.global [%0], [%1], 16;" :: "r"(dst), "l"(src));
}
__device__ __forceinline__ void cp_commit() { asm volatile("cp.async.commit_group;"); }
__device__ __forceinline__ void cp_wait0()  { asm volatile("cp.async.wait_group 0;"); }
__device__ __forceinline__ uint32_t tf32(float v) {
    uint32_t t; asm("cvt.rna.tf32.f32 %0, %1;" : "=r"(t) : "f"(v));
    return t;
}
__device__ __forceinline__ void mma8(float* c, const uint32_t* a, const uint32_t* b) {
    asm volatile(
        "mma.sync.aligned.m16n8k8.row.col.f32.tf32.tf32.f32 "
        "{%0,%1,%2,%3}, {%4,%5,%6,%7}, {%8,%9}, {%0,%1,%2,%3};"
        : "+f"(c[0]), "+f"(c[1]), "+f"(c[2]), "+f"(c[3])
        : "r"(a[0]), "r"(a[1]), "r"(a[2]), "r"(a[3]), "r"(b[0]), "r"(b[1]));
}

__device__ __align__(16) float g_part[(size_t)NNT0 * BB * JJ * PP];  // 16MB
__device__ __align__(16) float g_V[BB * JJ * PP];
__device__ float g_dummy;

__global__ void caps_dummy() { if (threadIdx.x == 0) g_dummy = 0.0f; }

// ============ pass0: mma.sync tf32 GEMM (R11/R13 verified) ============
__global__ void __launch_bounds__(256, 1)
caps_pass0_mma(const float* __restrict__ xg, const float* __restrict__ Wg)
{
    extern __shared__ __align__(16) float sm[];
    const unsigned sm0 = smem_u32(sm);

    const int tid = threadIdx.x;
    const int w   = tid >> 5;
    const int lane = tid & 31;
    const int g   = lane >> 2;
    const int tig = lane & 3;
    const int jh  = blockIdx.x & 1;
    const int kt  = blockIdx.x >> 1;
    const int koff0 = kt * 256;

    auto stage = [&](int st) {
        const unsigned bufA = sm0 + (unsigned)((st & 1) * BUF_F) * 4;
        const unsigned bufB = bufA + (unsigned)AS_F * 4;
        const int koff = koff0 + st * 32;
        #pragma unroll
        for (int q = 0; q < 4; q++) {
            int c = tid + q * 256, b = c >> 3, h = c & 7;
            cp16(bufA + (unsigned)(b * RS + h * 4) * 4,
                 xg + (size_t)b * (NN * DD) + koff + h * 4);
        }
        #pragma unroll
        for (int q = 0; q < 8; q++) {
            int c = tid + q * 256, r = c >> 3, h = c & 7;
            int j = jh * 16 + (r >> 4), p = r & 15;
            int n = (koff >> 3) + (h >> 1);
            cp16(bufB + (unsigned)(r * RS + h * 4) * 4,
                 Wg + ((size_t)j * NN + n) * 128 + p * 8 + (h & 1) * 4);
        }
        cp_commit();
    };

    stage(0);

    float C[8][4][4];
    #pragma unroll
    for (int mt = 0; mt < 8; mt++)
        #pragma unroll
        for (int q = 0; q < 4; q++)
            #pragma unroll
            for (int e = 0; e < 4; e++) C[mt][q][e] = 0.0f;

    for (int st = 0; st < 8; st++) {
        cp_wait0();
        __syncthreads();
        if (st + 1 < 8) stage(st + 1);

        const float* As = sm + (st & 1) * BUF_F;
        const float* Bs = As + AS_F;

        #pragma unroll
        for (int kc = 0; kc < 4; kc++) {
            const int k0 = kc * 8 + tig;
            uint32_t Bf[4][2];
            #pragma unroll
            for (int q = 0; q < 4; q++) {
                const float* br = Bs + (w * 32 + q * 8 + g) * RS;
                Bf[q][0] = tf32(br[k0]);
                Bf[q][1] = tf32(br[k0 + 4]);
            }
            #pragma unroll
            for (int mt = 0; mt < 8; mt++) {
                const float* ar0 = As + (mt * 16 + g) * RS;
                const float* ar1 = ar0 + 8 * RS;
                uint32_t Af[4];
                Af[0] = tf32(ar0[k0]);
                Af[1] = tf32(ar1[k0]);
                Af[2] = tf32(ar0[k0 + 4]);
                Af[3] = tf32(ar1[k0 + 4]);
                #pragma unroll
                for (int q = 0; q < 4; q++) mma8(C[mt][q], Af, Bf[q]);
            }
        }
    }

    const float inv = 1.0f / 32.0f;
    #pragma unroll
    for (int mt = 0; mt < 8; mt++) {
        #pragma unroll
        for (int q = 0; q < 4; q++) {
            int jpg = jh * 256 + w * 32 + q * 8 + tig * 2;
            int j = jpg >> 4, p = jpg & 15;
            int b0 = mt * 16 + g;
            float* d0 = &g_part[(((size_t)kt * BB + b0) * JJ + j) * PP + p];
            float* d1 = &g_part[(((size_t)kt * BB + b0 + 8) * JJ + j) * PP + p];
            *reinterpret_cast<float2*>(d0) =
                make_float2(C[mt][q][0] * inv, C[mt][q][1] * inv);
            *reinterpret_cast<float2*>(d1) =
                make_float2(C[mt][q][2] * inv, C[mt][q][3] * inv);
        }
    }
}

// ============ pass1: mma u_hat + fragment-register softmax ============
// Thread (w, g, t): warp w owns j = w*4..w*4+3 (jp cols w*64..w*64+63).
// Per n: u_hat frags Cn[q][0..3] = u[b=g / g+8, jp = w*64+q*8+2t(+1)].
__global__ void __launch_bounds__(256)
caps_pass1_mma(const float* __restrict__ xg, const float* __restrict__ Wg)
{
    extern __shared__ __align__(16) float sm[];
    float* e_sh = sm + ESH_M;
    const unsigned sm0 = smem_u32(sm);

    const int tid  = threadIdx.x;
    const int w    = tid >> 5;
    const int lane = tid & 31;
    const int g    = lane >> 2;
    const int t    = lane & 3;
    const int bt   = blockIdx.x & 7;
    const int nt   = blockIdx.x >> 3;
    const int b0   = bt * 16;
    const int n0   = nt * NC1M;

    // V fragments: Vg[Q][.] = V[b0+g][w*4+Q][p in {2t,2t+1,8+2t,8+2t+1}]
    float Vg[4][4], Vh[4][4];
    #pragma unroll
    for (int Q = 0; Q < 4; Q++) {
        const float* vg = g_V + (size_t)(b0 + g) * 512 + (w * 4 + Q) * 16;
        const float* vh = g_V + (size_t)(b0 + g + 8) * 512 + (w * 4 + Q) * 16;
        float2 a = *reinterpret_cast<const float2*>(vg + 2 * t);
        float2 b = *reinterpret_cast<const float2*>(vg + 8 + 2 * t);
        Vg[Q][0] = a.x; Vg[Q][1] = a.y; Vg[Q][2] = b.x; Vg[Q][3] = b.y;
        float2 c = *reinterpret_cast<const float2*>(vh + 2 * t);
        float2 d = *reinterpret_cast<const float2*>(vh + 8 + 2 * t);
        Vh[Q][0] = c.x; Vh[Q][1] = c.y; Vh[Q][2] = d.x; Vh[Q][3] = d.y;
    }

    // W stage: row jp -> W_s[buf][jp*12 .. +8] (conflict-free stride 12)
    auto stageW = [&](int n) {
        const unsigned buf = sm0 + (unsigned)((n & 1) * WBUF_M) * 4;
        #pragma unroll
        for (int q = 0; q < 2; q++) {
            int jp = tid + q * 256;
            int j = jp >> 4, p = jp & 15;
            const float* src = Wg + ((size_t)j * NN + (n0 + n)) * 128 + p * 8;
            unsigned dst = buf + (unsigned)(jp * WROW) * 4;
            cp16(dst, src);
            cp16(dst + 16, src + 4);
        }
    };

    // prologue: x preload (16b x 128n x 8i = 64KB) + W(0), one group
    #pragma unroll
    for (int q = 0; q < 16; q++) {
        int c = tid + q * 256;               // 0..4095
        int n = c >> 5, b = (c >> 1) & 15, h = c & 1;
        cp16(sm0 + (unsigned)(XOFF_M + n * 128 + b * 8 + h * 4) * 4,
             xg + ((size_t)(b0 + b) * NN + (n0 + n)) * DD + h * 4);
    }
    stageW(0);
    cp_commit();

    float S[8][4];
    #pragma unroll
    for (int q = 0; q < 8; q++)
        #pragma unroll
        for (int e = 0; e < 4; e++) S[q][e] = 0.0f;

    for (int n = 0; n < NC1M; n++) {
        cp_wait0();
        __syncthreads();
        if (n + 1 < NC1M) { stageW(n + 1); cp_commit(); }

        // ---- A fragments (hi/lo split) ----
        const float* xb = sm + XOFF_M + n * 128;
        float a0 = xb[g * 8 + t];
        float a1 = xb[(g + 8) * 8 + t];
        float a2 = xb[g * 8 + t + 4];
        float a3 = xb[(g + 8) * 8 + t + 4];
        uint32_t Ah[4] = { tf32(a0), tf32(a1), tf32(a2), tf32(a3) };
        uint32_t Al[4] = {
            __float_as_uint(a0 - __uint_as_float(Ah[0])),
            __float_as_uint(a1 - __uint_as_float(Ah[1])),
            __float_as_uint(a2 - __uint_as_float(Ah[2])),
            __float_as_uint(a3 - __uint_as_float(Ah[3])) };

        // ---- u_hat via 3-mma split per tile ----
        const float* Wc = sm + (n & 1) * WBUF_M;
        float Cn[8][4];
        #pragma unroll
        for (int q = 0; q < 8; q++)
            #pragma unroll
            for (int e = 0; e < 4; e++) Cn[q][e] = 0.0f;

        #pragma unroll
        for (int q = 0; q < 8; q++) {
            const float* br = Wc + (w * 64 + q * 8 + g) * WROW;
            float b0f = br[t], b1f = br[t + 4];
            uint32_t Bh[2] = { tf32(b0f), tf32(b1f) };
            uint32_t Bl[2] = {
                __float_as_uint(b0f - __uint_as_float(Bh[0])),
                __float_as_uint(b1f - __uint_as_float(Bh[1])) };
            mma8(Cn[q], Ah, Bh);
            mma8(Cn[q], Ah, Bl);
            mma8(Cn[q], Al, Bh);
        }

        // ---- logits, folded over the quad (p spread across t) ----
        float Lg[4], Lh[4];
        #pragma unroll
        for (int Q = 0; Q < 4; Q++) {
            int q0 = 2 * Q, q1 = 2 * Q + 1;
            Lg[Q] = Cn[q0][0] * Vg[Q][0] + Cn[q0][1] * Vg[Q][1]
                  + Cn[q1][0] * Vg[Q][2] + Cn[q1][1] * Vg[Q][3];
            Lh[Q] = Cn[q0][2] * Vh[Q][0] + Cn[q0][3] * Vh[Q][1]
                  + Cn[q1][2] * Vh[Q][2] + Cn[q1][3] * Vh[Q][3];
        }
        #pragma unroll
        for (int Q = 0; Q < 4; Q++) {
            Lg[Q] += __shfl_xor_sync(0xffffffffu, Lg[Q], 1);
            Lg[Q] += __shfl_xor_sync(0xffffffffu, Lg[Q], 2);
            Lh[Q] += __shfl_xor_sync(0xffffffffu, Lh[Q], 1);
            Lh[Q] += __shfl_xor_sync(0xffffffffu, Lh[Q], 2);
        }

        // ---- exp: lane t handles j = w*4 + t (one exp per (b,j) total) ----
        float lg = (t == 0) ? Lg[0] : (t == 1) ? Lg[1] : (t == 2) ? Lg[2] : Lg[3];
        float lh = (t == 0) ? Lh[0] : (t == 1) ? Lh[1] : (t == 2) ? Lh[2] : Lh[3];
        float eg = __expf(lg);          // |logit| small: raw exp safe
        float eh = __expf(lh);

        // warp-local 4-j sums (fold over quad)
        float sg = eg + __shfl_xor_sync(0xffffffffu, eg, 1);
        sg += __shfl_xor_sync(0xffffffffu, sg, 2);
        float sh = eh + __shfl_xor_sync(0xffffffffu, eh, 1);
        sh += __shfl_xor_sync(0xffffffffu, sh, 2);
        if (t == 0) {
            e_sh[g * 12 + w]       = sg;
            e_sh[(g + 8) * 12 + w] = sh;
        }
        __syncthreads();

        // totals over 8 warps (32 j)
        float4 t0 = *reinterpret_cast<const float4*>(&e_sh[g * 12]);
        float4 t1 = *reinterpret_cast<const float4*>(&e_sh[g * 12 + 4]);
        float Tg = ((t0.x + t0.y) + (t0.z + t0.w)) + ((t1.x + t1.y) + (t1.z + t1.w));
        float4 t2 = *reinterpret_cast<const float4*>(&e_sh[(g + 8) * 12]);
        float4 t3 = *reinterpret_cast<const float4*>(&e_sh[(g + 8) * 12 + 4]);
        float Th = ((t2.x + t2.y) + (t2.z + t2.w)) + ((t3.x + t3.y) + (t3.z + t3.w));
        float rg = __frcp_rn(Tg), rh = __frcp_rn(Th);

        // redistribute e across quad, form c, accumulate s on fragments
        int base = lane & ~3;
        float cg[4], ch[4];
        #pragma unroll
        for (int Q = 0; Q < 4; Q++) {
            cg[Q] = __shfl_sync(0xffffffffu, eg, base + Q) * rg;
            ch[Q] = __shfl_sync(0xffffffffu, eh, base + Q) * rh;
        }
        #pragma unroll
        for (int q = 0; q < 8; q++) {
            int Q = q >> 1;
            S[q][0] = fmaf(cg[Q], Cn[q][0], S[q][0]);
            S[q][1] = fmaf(cg[Q], Cn[q][1], S[q][1]);
            S[q][2] = fmaf(ch[Q], Cn[q][2], S[q][2]);
            S[q][3] = fmaf(ch[Q], Cn[q][3], S[q][3]);
        }
    }

    // epilogue: g_part[nt][b][jp]  (jp = j*16+p flat)
    #pragma unroll
    for (int q = 0; q < 8; q++) {
        int jp = w * 64 + q * 8 + 2 * t;
        float* d0 = &g_part[((size_t)nt * BB + b0 + g) * 512 + jp];
        float* d1 = &g_part[((size_t)nt * BB + b0 + g + 8) * 512 + jp];
        *reinterpret_cast<float2*>(d0) = make_float2(S[q][0], S[q][1]);
        *reinterpret_cast<float2*>(d1) = make_float2(S[q][2], S[q][3]);
    }
}

// ============ reduce over nt (k-split 8 + shfl), squash, update V / out ====
__global__ void caps_squash(float* __restrict__ outg, int stage, int nnt)
{
    int t    = blockIdx.x * blockDim.x + threadIdx.x;
    int quad = t & 3;
    int k    = (t >> 2) & 7;
    int vec  = t >> 5;
    if (vec >= BB * JJ) return;

    float4 acc = make_float4(0.f, 0.f, 0.f, 0.f);
    int cnt = nnt >> 3;
    for (int ntk = 0; ntk < cnt; ntk++) {
        int nt = k * cnt + ntk;
        float4 v = *reinterpret_cast<const float4*>(
            &g_part[((size_t)nt * BB * JJ + vec) * PP + quad * 4]);
        acc.x += v.x; acc.y += v.y; acc.z += v.z; acc.w += v.w;
    }
    #pragma unroll
    for (int m = 4; m <= 16; m <<= 1) {
        acc.x += __shfl_xor_sync(0xffffffffu, acc.x, m);
        acc.y += __shfl_xor_sync(0xffffffffu, acc.y, m);
        acc.z += __shfl_xor_sync(0xffffffffu, acc.z, m);
        acc.w += __shfl_xor_sync(0xffffffffu, acc.w, m);
    }

    float s2 = acc.x * acc.x + acc.y * acc.y + acc.z * acc.z + acc.w * acc.w;
    s2 += __shfl_xor_sync(0xffffffffu, s2, 1);
    s2 += __shfl_xor_sync(0xffffffffu, s2, 2);

    float scale = s2 / ((1.0f + s2) * sqrtf(s2 + 1e-7f));
    float4 v4 = make_float4(acc.x * scale, acc.y * scale,
                            acc.z * scale, acc.w * scale);

    if (k == 0) {
        if (stage == 2) {
            *reinterpret_cast<float4*>(&outg[vec * PP + quad * 4]) = v4;
        } else if (stage == 0) {
            *reinterpret_cast<float4*>(&g_V[vec * PP + quad * 4]) = v4;
        } else {
            float4 cur = *reinterpret_cast<const float4*>(&g_V[vec * PP + quad * 4]);
            cur.x += v4.x; cur.y += v4.y; cur.z += v4.z; cur.w += v4.w;
            *reinterpret_cast<float4*>(&g_V[vec * PP + quad * 4]) = cur;
        }
    }
}

extern "C" void kernel_launch(void* const* d_in, const int* in_sizes, int n_in,
                              void* d_out, int out_size)
{
    const float* x = (const float*)d_in[0];
    const float* W = (const float*)d_in[1];
    if (n_in >= 2 && in_sizes[0] > in_sizes[1]) {
        const float* tmp = x; x = W; W = tmp;
    }
    float* out = (float*)d_out;

    cudaFuncSetAttribute(caps_pass0_mma,
        cudaFuncAttributeMaxDynamicSharedMemorySize, SMEM0_B);
    cudaFuncSetAttribute(caps_pass1_mma,
        cudaFuncAttributeMaxDynamicSharedMemorySize, SMEM1M_B);

    const int SQ_BLOCK = 256;
    const int SQ_GRID  = (BB * JJ * 32 + SQ_BLOCK - 1) / SQ_BLOCK;  // 512

    caps_dummy<<<1, 32>>>();                                  // 1 (slot 6 = pass1 #2)
    caps_pass0_mma<<<128, 256, SMEM0_B>>>(x, W);              // 2
    caps_squash<<<SQ_GRID, SQ_BLOCK>>>(out, 0, NNT0);         // 3: V = v0
    caps_pass1_mma<<<128, 256, SMEM1M_B>>>(x, W);             // 4
    caps_squash<<<SQ_GRID, SQ_BLOCK>>>(out, 1, NNT1M);        // 5: V += v1
    caps_pass1_mma<<<128, 256, SMEM1M_B>>>(x, W);             // 6 <- profiled
    caps_squash<<<SQ_GRID, SQ_BLOCK>>>(out, 2, NNT1M);        // 7: out
}

// round 15
// speedup vs baseline: 1.1925x; 1.1925x over previous
#include <cuda_runtime.h>
#include <cstdint>

// Capsule routing. x:[128,2048,8] W:[32,2048,16,8] out:[128,32,16]
// R15: R14's fragment-softmax pass1 with the resource bugs fixed:
//   - V in smem (transposed, conflict-free stride 20) -> no register spills
//   - grid 256 @ 2 CTAs/SM (NC=64) -> cross-CTA latency hiding, full chip
// pass0 = mma.sync tf32 GEMM (verified R11/R13).
// Identity: b_k = (sum_{i<k} v_i) . u_hat  ->  u_hat/b never materialized.

#define BB 128
#define NN 2048
#define DD 8
#define JJ 32
#define PP 16
#define NNT0 64

// pass1_mma: grid 256 = 8 bt x 32 nt; 16 b, 64 n per CTA; 256 thr (8 warps)
#define NC1M  64
#define NNT1M 32
#define WROW  12                        // W_s row stride: conflict-free
#define WBUF_M (512 * WROW)             // 6144 floats per stage
#define XOFF_M (2 * WBUF_M)             // 12288
#define XBUF   192                      // 16 b * stride 12
#define VOFF_M (XOFF_M + 2 * XBUF)      // 12672
#define EOFF_M (VOFF_M + 512 * 20)      // 22912
#define SMEM1M_B ((EOFF_M + 192) * 4)   // 92416 B

// pass0 mma smem: rows padded to 44 floats
#define RS    44
#define AS_F  (128 * RS)
#define BS_F  (256 * RS)
#define BUF_F (AS_F + BS_F)
#define SMEM0_B (2 * BUF_F * 4)         // 135168 B

__device__ __forceinline__ unsigned smem_u32(const void* p) {
    return (unsigned)__cvta_generic_to_shared(p);
}
__device__ __forceinline__ void cp16(unsigned dst, const void* src) {
    asm volatile("cp.async.cg.shared.global [%0], [%1], 16;" :: "r"(dst), "l"(src));
}
__device__ __forceinline__ void cp_commit() { asm volatile("cp.async.commit_group;"); }
__device__ __forceinline__ void cp_wait0()  { asm volatile("cp.async.wait_group 0;"); }
__device__ __forceinline__ uint32_t tf32(float v) {
    uint32_t t; asm("cvt.rna.tf32.f32 %0, %1;" : "=r"(t) : "f"(v));
    return t;
}
__device__ __forceinline__ void mma8(float* c, const uint32_t* a, const uint32_t* b) {
    asm volatile(
        "mma.sync.aligned.m16n8k8.row.col.f32.tf32.tf32.f32 "
        "{%0,%1,%2,%3}, {%4,%5,%6,%7}, {%8,%9}, {%0,%1,%2,%3};"
        : "+f"(c[0]), "+f"(c[1]), "+f"(c[2]), "+f"(c[3])
        : "r"(a[0]), "r"(a[1]), "r"(a[2]), "r"(a[3]), "r"(b[0]), "r"(b[1]));
}

__device__ __align__(16) float g_part[(size_t)NNT0 * BB * JJ * PP];  // 16MB
__device__ __align__(16) float g_V[BB * JJ * PP];
__device__ float g_dummy;

__global__ void caps_dummy() { if (threadIdx.x == 0) g_dummy = 0.0f; }

// ============ pass0: mma.sync tf32 GEMM (R11/R13 verified) ============
__global__ void __launch_bounds__(256, 1)
caps_pass0_mma(const float* __restrict__ xg, const float* __restrict__ Wg)
{
    extern __shared__ __align__(16) float sm[];
    const unsigned sm0 = smem_u32(sm);

    const int tid = threadIdx.x;
    const int w   = tid >> 5;
    const int lane = tid & 31;
    const int g   = lane >> 2;
    const int tig = lane & 3;
    const int jh  = blockIdx.x & 1;
    const int kt  = blockIdx.x >> 1;
    const int koff0 = kt * 256;

    auto stage = [&](int st) {
        const unsigned bufA = sm0 + (unsigned)((st & 1) * BUF_F) * 4;
        const unsigned bufB = bufA + (unsigned)AS_F * 4;
        const int koff = koff0 + st * 32;
        #pragma unroll
        for (int q = 0; q < 4; q++) {
            int c = tid + q * 256, b = c >> 3, h = c & 7;
            cp16(bufA + (unsigned)(b * RS + h * 4) * 4,
                 xg + (size_t)b * (NN * DD) + koff + h * 4);
        }
        #pragma unroll
        for (int q = 0; q < 8; q++) {
            int c = tid + q * 256, r = c >> 3, h = c & 7;
            int j = jh * 16 + (r >> 4), p = r & 15;
            int n = (koff >> 3) + (h >> 1);
            cp16(bufB + (unsigned)(r * RS + h * 4) * 4,
                 Wg + ((size_t)j * NN + n) * 128 + p * 8 + (h & 1) * 4);
        }
        cp_commit();
    };

    stage(0);

    float C[8][4][4];
    #pragma unroll
    for (int mt = 0; mt < 8; mt++)
        #pragma unroll
        for (int q = 0; q < 4; q++)
            #pragma unroll
            for (int e = 0; e < 4; e++) C[mt][q][e] = 0.0f;

    for (int st = 0; st < 8; st++) {
        cp_wait0();
        __syncthreads();
        if (st + 1 < 8) stage(st + 1);

        const float* As = sm + (st & 1) * BUF_F;
        const float* Bs = As + AS_F;

        #pragma unroll
        for (int kc = 0; kc < 4; kc++) {
            const int k0 = kc * 8 + tig;
            uint32_t Bf[4][2];
            #pragma unroll
            for (int q = 0; q < 4; q++) {
                const float* br = Bs + (w * 32 + q * 8 + g) * RS;
                Bf[q][0] = tf32(br[k0]);
                Bf[q][1] = tf32(br[k0 + 4]);
            }
            #pragma unroll
            for (int mt = 0; mt < 8; mt++) {
                const float* ar0 = As + (mt * 16 + g) * RS;
                const float* ar1 = ar0 + 8 * RS;
                uint32_t Af[4];
                Af[0] = tf32(ar0[k0]);
                Af[1] = tf32(ar1[k0]);
                Af[2] = tf32(ar0[k0 + 4]);
                Af[3] = tf32(ar1[k0 + 4]);
                #pragma unroll
                for (int q = 0; q < 4; q++) mma8(C[mt][q], Af, Bf[q]);
            }
        }
    }

    const float inv = 1.0f / 32.0f;
    #pragma unroll
    for (int mt = 0; mt < 8; mt++) {
        #pragma unroll
        for (int q = 0; q < 4; q++) {
            int jpg = jh * 256 + w * 32 + q * 8 + tig * 2;
            int j = jpg >> 4, p = jpg & 15;
            int b0 = mt * 16 + g;
            float* d0 = &g_part[(((size_t)kt * BB + b0) * JJ + j) * PP + p];
            float* d1 = &g_part[(((size_t)kt * BB + b0 + 8) * JJ + j) * PP + p];
            *reinterpret_cast<float2*>(d0) =
                make_float2(C[mt][q][0] * inv, C[mt][q][1] * inv);
            *reinterpret_cast<float2*>(d1) =
                make_float2(C[mt][q][2] * inv, C[mt][q][3] * inv);
        }
    }
}

// ============ pass1: mma u_hat + fragment softmax, V in smem ============
// warp w owns j = w*4..w*4+3 (jp cols w*64..w*64+63); thread frag rows b=g,g+8.
__global__ void __launch_bounds__(256, 2)
caps_pass1_mma(const float* __restrict__ xg, const float* __restrict__ Wg)
{
    extern __shared__ __align__(16) float sm[];
    float* e_sh = sm + EOFF_M;
    const unsigned sm0 = smem_u32(sm);

    const int tid  = threadIdx.x;
    const int w    = tid >> 5;
    const int lane = tid & 31;
    const int g    = lane >> 2;
    const int t    = lane & 3;
    const int bt   = blockIdx.x & 7;
    const int nt   = blockIdx.x >> 3;
    const int b0   = bt * 16;
    const int n0   = nt * NC1M;

    // V -> smem transposed: V_s[jp*20 + b] (stride 20: conflict-free reads)
    #pragma unroll
    for (int q = 0; q < 32; q++) {
        int idx = tid + q * 256;           // 0..8191
        int b = idx >> 9;                  // 0..15
        int jp = idx & 511;
        sm[VOFF_M + jp * 20 + b] = g_V[(size_t)(b0 + b) * 512 + jp];
    }

    // stage W (512 rows x 8 floats, stride 12) + x (16 b, stride 12) for n
    auto stageW = [&](int n) {
        const unsigned buf = sm0 + (unsigned)((n & 1) * WBUF_M) * 4;
        #pragma unroll
        for (int q = 0; q < 2; q++) {
            int jp = tid + q * 256;
            int j = jp >> 4, p = jp & 15;
            const float* src = Wg + ((size_t)j * NN + (n0 + n)) * 128 + p * 8;
            unsigned dst = buf + (unsigned)(jp * WROW) * 4;
            cp16(dst, src);
            cp16(dst + 16, src + 4);
        }
        if (tid < 32) {
            int b = tid >> 1, h = tid & 1;
            cp16(sm0 + (unsigned)(XOFF_M + (n & 1) * XBUF + b * 12 + h * 4) * 4,
                 xg + ((size_t)(b0 + b) * NN + (n0 + n)) * DD + h * 4);
        }
        cp_commit();
    };

    stageW(0);

    float S[8][4];
    #pragma unroll
    for (int q = 0; q < 8; q++)
        #pragma unroll
        for (int e = 0; e < 4; e++) S[q][e] = 0.0f;

    for (int n = 0; n < NC1M; n++) {
        cp_wait0();
        __syncthreads();                  // W(n), x(n), V_s all visible
        if (n + 1 < NC1M) stageW(n + 1);

        // ---- A fragments (hi/lo split) ----
        const float* xb = sm + XOFF_M + (n & 1) * XBUF;
        float a0 = xb[g * 12 + t];
        float a1 = xb[(g + 8) * 12 + t];
        float a2 = xb[g * 12 + t + 4];
        float a3 = xb[(g + 8) * 12 + t + 4];
        uint32_t Ah[4] = { tf32(a0), tf32(a1), tf32(a2), tf32(a3) };
        uint32_t Al[4] = {
            __float_as_uint(a0 - __uint_as_float(Ah[0])),
            __float_as_uint(a1 - __uint_as_float(Ah[1])),
            __float_as_uint(a2 - __uint_as_float(Ah[2])),
            __float_as_uint(a3 - __uint_as_float(Ah[3])) };

        // ---- u_hat via 3-mma hi/lo split (fp32-class) ----
        const float* Wc = sm + (n & 1) * WBUF_M;
        float Cn[8][4];
        #pragma unroll
        for (int q = 0; q < 8; q++)
            #pragma unroll
            for (int e = 0; e < 4; e++) Cn[q][e] = 0.0f;

        #pragma unroll
        for (int q = 0; q < 8; q++) {
            const float* br = Wc + (w * 64 + q * 8 + g) * WROW;
            float b0f = br[t], b1f = br[t + 4];
            uint32_t Bh[2] = { tf32(b0f), tf32(b1f) };
            uint32_t Bl[2] = {
                __float_as_uint(b0f - __uint_as_float(Bh[0])),
                __float_as_uint(b1f - __uint_as_float(Bh[1])) };
            mma8(Cn[q], Ah, Bh);
            mma8(Cn[q], Ah, Bl);
            mma8(Cn[q], Al, Bh);
        }

        // ---- logits: V from smem (short lifetimes), quad folds ----
        float Lg[4], Lh[4];
        #pragma unroll
        for (int Q = 0; Q < 4; Q++) {
            const float* v0 = sm + VOFF_M + (w * 64 + Q * 16 + 2 * t) * 20;
            const float* v1 = v0 + 20;
            const float* v2 = sm + VOFF_M + (w * 64 + Q * 16 + 8 + 2 * t) * 20;
            const float* v3 = v2 + 20;
            int q0 = 2 * Q, q1 = 2 * Q + 1;
            Lg[Q] = Cn[q0][0] * v0[g] + Cn[q0][1] * v1[g]
                  + Cn[q1][0] * v2[g] + Cn[q1][1] * v3[g];
            Lh[Q] = Cn[q0][2] * v0[g + 8] + Cn[q0][3] * v1[g + 8]
                  + Cn[q1][2] * v2[g + 8] + Cn[q1][3] * v3[g + 8];
        }
        #pragma unroll
        for (int Q = 0; Q < 4; Q++) {
            Lg[Q] += __shfl_xor_sync(0xffffffffu, Lg[Q], 1);
            Lg[Q] += __shfl_xor_sync(0xffffffffu, Lg[Q], 2);
            Lh[Q] += __shfl_xor_sync(0xffffffffu, Lh[Q], 1);
            Lh[Q] += __shfl_xor_sync(0xffffffffu, Lh[Q], 2);
        }

        // ---- exp: lane t owns j = w*4 + t ----
        float lg = (t == 0) ? Lg[0] : (t == 1) ? Lg[1] : (t == 2) ? Lg[2] : Lg[3];
        float lh = (t == 0) ? Lh[0] : (t == 1) ? Lh[1] : (t == 2) ? Lh[2] : Lh[3];
        float eg = __expf(lg);            // |logit| small: raw exp safe
        float eh = __expf(lh);

        float sg = eg + __shfl_xor_sync(0xffffffffu, eg, 1);
        sg += __shfl_xor_sync(0xffffffffu, sg, 2);
        float sh = eh + __shfl_xor_sync(0xffffffffu, eh, 1);
        sh += __shfl_xor_sync(0xffffffffu, sh, 2);
        if (t == 0) {
            e_sh[g * 12 + w]       = sg;
            e_sh[(g + 8) * 12 + w] = sh;
        }
        __syncthreads();

        float4 t0 = *reinterpret_cast<const float4*>(&e_sh[g * 12]);
        float4 t1 = *reinterpret_cast<const float4*>(&e_sh[g * 12 + 4]);
        float Tg = ((t0.x + t0.y) + (t0.z + t0.w)) + ((t1.x + t1.y) + (t1.z + t1.w));
        float4 t2 = *reinterpret_cast<const float4*>(&e_sh[(g + 8) * 12]);
        float4 t3 = *reinterpret_cast<const float4*>(&e_sh[(g + 8) * 12 + 4]);
        float Th = ((t2.x + t2.y) + (t2.z + t2.w)) + ((t3.x + t3.y) + (t3.z + t3.w));
        float rg = __frcp_rn(Tg), rh = __frcp_rn(Th);

        int base = lane & ~3;
        float cg[4], ch[4];
        #pragma unroll
        for (int Q = 0; Q < 4; Q++) {
            cg[Q] = __shfl_sync(0xffffffffu, eg, base + Q) * rg;
            ch[Q] = __shfl_sync(0xffffffffu, eh, base + Q) * rh;
        }
        #pragma unroll
        for (int q = 0; q < 8; q++) {
            int Q = q >> 1;
            S[q][0] = fmaf(cg[Q], Cn[q][0], S[q][0]);
            S[q][1] = fmaf(cg[Q], Cn[q][1], S[q][1]);
            S[q][2] = fmaf(ch[Q], Cn[q][2], S[q][2]);
            S[q][3] = fmaf(ch[Q], Cn[q][3], S[q][3]);
        }
    }

    // epilogue: g_part[nt][b][jp]
    #pragma unroll
    for (int q = 0; q < 8; q++) {
        int jp = w * 64 + q * 8 + 2 * t;
        float* d0 = &g_part[((size_t)nt * BB + b0 + g) * 512 + jp];
        float* d1 = &g_part[((size_t)nt * BB + b0 + g + 8) * 512 + jp];
        *reinterpret_cast<float2*>(d0) = make_float2(S[q][0], S[q][1]);
        *reinterpret_cast<float2*>(d1) = make_float2(S[q][2], S[q][3]);
    }
}

// ============ reduce over nt (k-split 8 + shfl), squash, update V / out ====
__global__ void caps_squash(float* __restrict__ outg, int stage, int nnt)
{
    int t    = blockIdx.x * blockDim.x + threadIdx.x;
    int quad = t & 3;
    int k    = (t >> 2) & 7;
    int vec  = t >> 5;
    if (vec >= BB * JJ) return;

    float4 acc = make_float4(0.f, 0.f, 0.f, 0.f);
    int cnt = nnt >> 3;
    for (int ntk = 0; ntk < cnt; ntk++) {
        int nt = k * cnt + ntk;
        float4 v = *reinterpret_cast<const float4*>(
            &g_part[((size_t)nt * BB * JJ + vec) * PP + quad * 4]);
        acc.x += v.x; acc.y += v.y; acc.z += v.z; acc.w += v.w;
    }
    #pragma unroll
    for (int m = 4; m <= 16; m <<= 1) {
        acc.x += __shfl_xor_sync(0xffffffffu, acc.x, m);
        acc.y += __shfl_xor_sync(0xffffffffu, acc.y, m);
        acc.z += __shfl_xor_sync(0xffffffffu, acc.z, m);
        acc.w += __shfl_xor_sync(0xffffffffu, acc.w, m);
    }

    float s2 = acc.x * acc.x + acc.y * acc.y + acc.z * acc.z + acc.w * acc.w;
    s2 += __shfl_xor_sync(0xffffffffu, s2, 1);
    s2 += __shfl_xor_sync(0xffffffffu, s2, 2);

    float scale = s2 / ((1.0f + s2) * sqrtf(s2 + 1e-7f));
    float4 v4 = make_float4(acc.x * scale, acc.y * scale,
                            acc.z * scale, acc.w * scale);

    if (k == 0) {
        if (stage == 2) {
            *reinterpret_cast<float4*>(&outg[vec * PP + quad * 4]) = v4;
        } else if (stage == 0) {
            *reinterpret_cast<float4*>(&g_V[vec * PP + quad * 4]) = v4;
        } else {
            float4 cur = *reinterpret_cast<const float4*>(&g_V[vec * PP + quad * 4]);
            cur.x += v4.x; cur.y += v4.y; cur.z += v4.z; cur.w += v4.w;
            *reinterpret_cast<float4*>(&g_V[vec * PP + quad * 4]) = cur;
        }
    }
}

extern "C" void kernel_launch(void* const* d_in, const int* in_sizes, int n_in,
                              void* d_out, int out_size)
{
    const float* x = (const float*)d_in[0];
    const float* W = (const float*)d_in[1];
    if (n_in >= 2 && in_sizes[0] > in_sizes[1]) {
        const float* tmp = x; x = W; W = tmp;
    }
    float* out = (float*)d_out;

    cudaFuncSetAttribute(caps_pass0_mma,
        cudaFuncAttributeMaxDynamicSharedMemorySize, SMEM0_B);
    cudaFuncSetAttribute(caps_pass1_mma,
        cudaFuncAttributeMaxDynamicSharedMemorySize, SMEM1M_B);

    const int SQ_BLOCK = 256;
    const int SQ_GRID  = (BB * JJ * 32 + SQ_BLOCK - 1) / SQ_BLOCK;  // 512

    caps_dummy<<<1, 32>>>();                                  // 1 (slot 6 = pass1 #2)
    caps_pass0_mma<<<128, 256, SMEM0_B>>>(x, W);              // 2
    caps_squash<<<SQ_GRID, SQ_BLOCK>>>(out, 0, NNT0);         // 3: V = v0
    caps_pass1_mma<<<256, 256, SMEM1M_B>>>(x, W);             // 4
    caps_squash<<<SQ_GRID, SQ_BLOCK>>>(out, 1, NNT1M);        // 5: V += v1
    caps_pass1_mma<<<256, 256, SMEM1M_B>>>(x, W);             // 6 <- profiled
    caps_squash<<<SQ_GRID, SQ_BLOCK>>>(out, 2, NNT1M);        // 7: out
}

// round 16
// speedup vs baseline: 1.5832x; 1.3276x over previous
#include <cuda_runtime.h>
#include <cstdint>

// Capsule routing. x:[128,2048,8] W:[32,2048,16,8] out:[128,32,16]
// R16 = R13 baseline (pass0 mma.sync tf32 GEMM + SIMT routed pass) with the
// routed pass remapped to lane=j: softmax sum is a warp shfl butterfly ->
// one barrier per n (W buffer only), no e_sh. mma-for-pass1 abandoned
// (R14/R15: fragment glue overhead > SIMT). b_k = (sum_{i<k} v_i) . u_hat.

#define BB 128
#define NN 2048
#define DD 8
#define JJ 32
#define PP 16
#define TPB 128
#define BT1  16
#define NC1  64
#define NBT1 8
#define NNT1 32
#define NNT0 64
#define WJS  132
#define WBUF (JJ * WJS)
#define XOFF (3 * WBUF)
#define X1F  (NC1 * BT1 * DD)
#define SMEM1_B ((XOFF + X1F) * 4)

// pass0 mma smem: rows padded to 44 floats (176B): conflict-free frag loads
#define RS    44
#define AS_F  (128 * RS)
#define BS_F  (256 * RS)
#define BUF_F (AS_F + BS_F)
#define SMEM0_B (2 * BUF_F * 4)     // 135168 B

typedef unsigned long long u64;

__device__ __forceinline__ u64 fma2(u64 a, u64 b, u64 c) {
    u64 d; asm("fma.rn.f32x2 %0, %1, %2, %3;" : "=l"(d) : "l"(a), "l"(b), "l"(c));
    return d;
}
__device__ __forceinline__ u64 mul2(u64 a, u64 b) {
    u64 d; asm("mul.rn.f32x2 %0, %1, %2;" : "=l"(d) : "l"(a), "l"(b));
    return d;
}
__device__ __forceinline__ float lohi_add(u64 v) {
    float a, b; asm("mov.b64 {%0, %1}, %2;" : "=f"(a), "=f"(b) : "l"(v));
    return a + b;
}
__device__ __forceinline__ unsigned smem_u32(const void* p) {
    return (unsigned)__cvta_generic_to_shared(p);
}
__device__ __forceinline__ void cp16(unsigned dst, const void* src) {
    asm volatile("cp.async.cg.shared.global [%0], [%1], 16;" :: "r"(dst), "l"(src));
}
__device__ __forceinline__ void cp_commit() { asm volatile("cp.async.commit_group;"); }
__device__ __forceinline__ void cp_wait1()  { asm volatile("cp.async.wait_group 1;"); }
__device__ __forceinline__ void cp_wait0()  { asm volatile("cp.async.wait_group 0;"); }
__device__ __forceinline__ uint32_t tf32(float v) {
    uint32_t t; asm("cvt.rna.tf32.f32 %0, %1;" : "=r"(t) : "f"(v));
    return t;
}
__device__ __forceinline__ void mma8(float* c, const uint32_t* a, const uint32_t* b) {
    asm volatile(
        "mma.sync.aligned.m16n8k8.row.col.f32.tf32.tf32.f32 "
        "{%0,%1,%2,%3}, {%4,%5,%6,%7}, {%8,%9}, {%0,%1,%2,%3};"
        : "+f"(c[0]), "+f"(c[1]), "+f"(c[2]), "+f"(c[3])
        : "r"(a[0]), "r"(a[1]), "r"(a[2]), "r"(a[3]), "r"(b[0]), "r"(b[1]));
}

__device__ __align__(16) float g_part[(size_t)NNT0 * BB * JJ * PP];  // 16MB
__device__ __align__(16) float g_V[BB * JJ * PP];
__device__ float g_dummy;

__global__ void caps_dummy() { if (threadIdx.x == 0) g_dummy = 0.0f; }

// ============ pass0: mma.sync tf32 GEMM (R11/R13 verified) ============
__global__ void __launch_bounds__(256, 1)
caps_pass0_mma(const float* __restrict__ xg, const float* __restrict__ Wg)
{
    extern __shared__ __align__(16) float sm[];
    const unsigned sm0 = smem_u32(sm);

    const int tid = threadIdx.x;
    const int w   = tid >> 5;
    const int lane = tid & 31;
    const int g   = lane >> 2;
    const int tig = lane & 3;
    const int jh  = blockIdx.x & 1;
    const int kt  = blockIdx.x >> 1;
    const int koff0 = kt * 256;

    auto stage = [&](int st) {
        const unsigned bufA = sm0 + (unsigned)((st & 1) * BUF_F) * 4;
        const unsigned bufB = bufA + (unsigned)AS_F * 4;
        const int koff = koff0 + st * 32;
        #pragma unroll
        for (int q = 0; q < 4; q++) {
            int c = tid + q * 256, b = c >> 3, h = c & 7;
            cp16(bufA + (unsigned)(b * RS + h * 4) * 4,
                 xg + (size_t)b * (NN * DD) + koff + h * 4);
        }
        #pragma unroll
        for (int q = 0; q < 8; q++) {
            int c = tid + q * 256, r = c >> 3, h = c & 7;
            int j = jh * 16 + (r >> 4), p = r & 15;
            int n = (koff >> 3) + (h >> 1);
            cp16(bufB + (unsigned)(r * RS + h * 4) * 4,
                 Wg + ((size_t)j * NN + n) * 128 + p * 8 + (h & 1) * 4);
        }
        cp_commit();
    };

    stage(0);

    float C[8][4][4];
    #pragma unroll
    for (int mt = 0; mt < 8; mt++)
        #pragma unroll
        for (int q = 0; q < 4; q++)
            #pragma unroll
            for (int e = 0; e < 4; e++) C[mt][q][e] = 0.0f;

    for (int st = 0; st < 8; st++) {
        cp_wait0();
        __syncthreads();
        if (st + 1 < 8) stage(st + 1);

        const float* As = sm + (st & 1) * BUF_F;
        const float* Bs = As + AS_F;

        #pragma unroll
        for (int kc = 0; kc < 4; kc++) {
            const int k0 = kc * 8 + tig;
            uint32_t Bf[4][2];
            #pragma unroll
            for (int q = 0; q < 4; q++) {
                const float* br = Bs + (w * 32 + q * 8 + g) * RS;
                Bf[q][0] = tf32(br[k0]);
                Bf[q][1] = tf32(br[k0 + 4]);
            }
            #pragma unroll
            for (int mt = 0; mt < 8; mt++) {
                const float* ar0 = As + (mt * 16 + g) * RS;
                const float* ar1 = ar0 + 8 * RS;
                uint32_t Af[4];
                Af[0] = tf32(ar0[k0]);
                Af[1] = tf32(ar1[k0]);
                Af[2] = tf32(ar0[k0 + 4]);
                Af[3] = tf32(ar1[k0 + 4]);
                #pragma unroll
                for (int q = 0; q < 4; q++) mma8(C[mt][q], Af, Bf[q]);
            }
        }
    }

    const float inv = 1.0f / 32.0f;
    #pragma unroll
    for (int mt = 0; mt < 8; mt++) {
        #pragma unroll
        for (int q = 0; q < 4; q++) {
            int jpg = jh * 256 + w * 32 + q * 8 + tig * 2;
            int j = jpg >> 4, p = jpg & 15;
            int b0 = mt * 16 + g;
            float* d0 = &g_part[(((size_t)kt * BB + b0) * JJ + j) * PP + p];
            float* d1 = &g_part[(((size_t)kt * BB + b0 + 8) * JJ + j) * PP + p];
            *reinterpret_cast<float2*>(d0) =
                make_float2(C[mt][q][0] * inv, C[mt][q][1] * inv);
            *reinterpret_cast<float2*>(d1) =
                make_float2(C[mt][q][2] * inv, C[mt][q][3] * inv);
        }
    }
}

// ============ pass1: SIMT routed pass, lane = j (warp-local softmax) ========
// Warp w owns b = b0 + w*4 + r (r=0..3); lane = j. One barrier per n.
__global__ void __launch_bounds__(TPB, 2)
caps_pass1(const float* __restrict__ xg, const float* __restrict__ Wg)
{
    extern __shared__ __align__(16) float sm[];
    const unsigned sm0 = smem_u32(sm);

    const int tid  = threadIdx.x;
    const int lane = tid & 31;          // = j
    const int w    = tid >> 5;          // warp: 4 b's
    const int j    = lane;
    const int bt   = blockIdx.x & (NBT1 - 1);
    const int nt   = blockIdx.x >> 3;
    const int b0   = bt * BT1;
    const int n0   = nt * NC1;

    // V[b][j][:] for the warp's 4 b's, packed p-pairs
    u64 V2[4][8];
    #pragma unroll
    for (int r = 0; r < 4; r++) {
        const ulonglong2* vp = reinterpret_cast<const ulonglong2*>(
            &g_V[((size_t)(b0 + w * 4 + r) * JJ + j) * PP]);
        #pragma unroll
        for (int q = 0; q < 4; q++) {
            ulonglong2 t = vp[q]; V2[r][2*q] = t.x; V2[r][2*q+1] = t.y;
        }
    }

    const int jb = tid >> 5, cc = tid & 31;
    const float* wbase = Wg + (size_t)jb * NN * 128 + cc * 4;
    const unsigned wdst0 = sm0 + (unsigned)(jb * WJS + cc * 4) * 4;

    #pragma unroll
    for (int q = 0; q < 16; q++) {
        int c = tid + q * TPB;
        int n = c >> 5, b = (c >> 1) & 15, h = c & 1;
        cp16(sm0 + (unsigned)(XOFF + n * (BT1*DD) + b * DD + h * 4) * 4,
             xg + ((size_t)(b0 + b) * NN + (n0 + n)) * DD + h * 4);
    }
    #pragma unroll
    for (int q = 0; q < 8; q++)
        cp16(wdst0 + q * (4*WJS*4),
             wbase + (size_t)n0 * 128 + (size_t)q * 4 * NN * 128);
    cp_commit();
    #pragma unroll
    for (int q = 0; q < 8; q++)
        cp16(wdst0 + (unsigned)(WBUF*4) + q * (4*WJS*4),
             wbase + (size_t)(n0+1) * 128 + (size_t)q * 4 * NN * 128);
    cp_commit();

    u64 s2[4][8];
    #pragma unroll
    for (int r = 0; r < 4; r++)
        #pragma unroll
        for (int q = 0; q < 8; q++) s2[r][q] = 0ull;

    int cur = 0, pf = 2;
    for (int nn = 0; nn < NC1; nn++) {
        if (nn >= NC1 - 2) cp_wait0(); else cp_wait1();
        __syncthreads();
        if (nn + 2 < NC1) {
            unsigned d = wdst0 + (unsigned)(pf * WBUF) * 4;
            const float* s = wbase + (size_t)(n0 + nn + 2) * 128;
            #pragma unroll
            for (int q = 0; q < 8; q++)
                cp16(d + q * (4*WJS*4), s + (size_t)q * 4 * NN * 128);
            cp_commit();
        }

        // x for the warp's 4 b's (broadcast across lanes)
        const float* xrow = sm + XOFF + nn * (BT1*DD);
        u64 X[4][4];
        #pragma unroll
        for (int r = 0; r < 4; r++) {
            const ulonglong2* xp =
                reinterpret_cast<const ulonglong2*>(xrow + (w * 4 + r) * DD);
            ulonglong2 t0 = xp[0], t1 = xp[1];
            X[r][0] = t0.x; X[r][1] = t0.y; X[r][2] = t1.x; X[r][3] = t1.y;
        }

        // u_hat: lane's own j row (32 distinct rows; 4-bank skew -> data-floor wf)
        const float* Wj = sm + cur * WBUF + j * WJS;
        u64 u2[4][8];
        #pragma unroll
        for (int p2 = 0; p2 < 8; p2++) {
            const ulonglong2* wr = reinterpret_cast<const ulonglong2*>(Wj + p2 * 16);
            ulonglong2 w0 = wr[0], w1 = wr[1], w2 = wr[2], w3 = wr[3];
            #pragma unroll
            for (int r = 0; r < 4; r++) {
                u64 a = mul2(w0.x, X[r][0]);
                a = fma2(w0.y, X[r][1], a);
                a = fma2(w1.x, X[r][2], a);
                a = fma2(w1.y, X[r][3], a);
                u64 b = mul2(w2.x, X[r][0]);
                b = fma2(w2.y, X[r][1], b);
                b = fma2(w3.x, X[r][2], b);
                b = fma2(w3.y, X[r][3], b);
                u64 pr; asm("mov.b64 %0, {%1, %2};" : "=l"(pr)
                            : "f"(lohi_add(a)), "f"(lohi_add(b)));
                u2[r][p2] = pr;
            }
        }

        // logits + exp (one per (b,j); this thread IS (b=w*4+r, j=lane))
        float e[4];
        #pragma unroll
        for (int r = 0; r < 4; r++) {
            u64 la = mul2(V2[r][0], u2[r][0]);
            u64 lb = mul2(V2[r][1], u2[r][1]);
            la = fma2(V2[r][2], u2[r][2], la);
            lb = fma2(V2[r][3], u2[r][3], lb);
            la = fma2(V2[r][4], u2[r][4], la);
            lb = fma2(V2[r][5], u2[r][5], lb);
            la = fma2(V2[r][6], u2[r][6], la);
            lb = fma2(V2[r][7], u2[r][7], lb);
            e[r] = __expf(lohi_add(la) + lohi_add(lb));   // |logit| small
        }

        // warp butterfly: sum over all 32 j, per r. No barrier, no smem.
        float sum[4];
        #pragma unroll
        for (int r = 0; r < 4; r++) sum[r] = e[r];
        #pragma unroll
        for (int m = 1; m < 32; m <<= 1) {
            #pragma unroll
            for (int r = 0; r < 4; r++)
                sum[r] += __shfl_xor_sync(0xffffffffu, sum[r], m);
        }

        #pragma unroll
        for (int r = 0; r < 4; r++) {
            float c = e[r] * __frcp_rn(sum[r]);
            u64 c2; asm("mov.b64 %0, {%1, %1};" : "=l"(c2) : "f"(c));
            #pragma unroll
            for (int q = 0; q < 8; q++) s2[r][q] = fma2(c2, u2[r][q], s2[r][q]);
        }

        cur = (cur == 2) ? 0 : cur + 1;
        pf  = (pf  == 2) ? 0 : pf  + 1;
    }

    // epilogue: coalesced (j = lane -> consecutive 64B rows)
    #pragma unroll
    for (int r = 0; r < 4; r++) {
        ulonglong2* dst = reinterpret_cast<ulonglong2*>(
            &g_part[(((size_t)nt * BB + b0 + w * 4 + r) * JJ + j) * PP]);
        #pragma unroll
        for (int q = 0; q < 4; q++) {
            ulonglong2 t; t.x = s2[r][2*q]; t.y = s2[r][2*q+1]; dst[q] = t;
        }
    }
}

// ============ reduce over nt (k-split 8 + shfl), squash, update V / out ====
__global__ void caps_squash(float* __restrict__ outg, int stage, int nnt)
{
    int t    = blockIdx.x * blockDim.x + threadIdx.x;
    int quad = t & 3;
    int k    = (t >> 2) & 7;
    int vec  = t >> 5;
    if (vec >= BB * JJ) return;

    float4 acc = make_float4(0.f, 0.f, 0.f, 0.f);
    int cnt = nnt >> 3;
    for (int ntk = 0; ntk < cnt; ntk++) {
        int nt = k * cnt + ntk;
        float4 v = *reinterpret_cast<const float4*>(
            &g_part[((size_t)nt * BB * JJ + vec) * PP + quad * 4]);
        acc.x += v.x; acc.y += v.y; acc.z += v.z; acc.w += v.w;
    }
    #pragma unroll
    for (int m = 4; m <= 16; m <<= 1) {
        acc.x += __shfl_xor_sync(0xffffffffu, acc.x, m);
        acc.y += __shfl_xor_sync(0xffffffffu, acc.y, m);
        acc.z += __shfl_xor_sync(0xffffffffu, acc.z, m);
        acc.w += __shfl_xor_sync(0xffffffffu, acc.w, m);
    }

    float s2 = acc.x * acc.x + acc.y * acc.y + acc.z * acc.z + acc.w * acc.w;
    s2 += __shfl_xor_sync(0xffffffffu, s2, 1);
    s2 += __shfl_xor_sync(0xffffffffu, s2, 2);

    float scale = s2 / ((1.0f + s2) * sqrtf(s2 + 1e-7f));
    float4 v4 = make_float4(acc.x * scale, acc.y * scale,
                            acc.z * scale, acc.w * scale);

    if (k == 0) {
        if (stage == 2) {
            *reinterpret_cast<float4*>(&outg[vec * PP + quad * 4]) = v4;
        } else if (stage == 0) {
            *reinterpret_cast<float4*>(&g_V[vec * PP + quad * 4]) = v4;
        } else {
            float4 cur = *reinterpret_cast<const float4*>(&g_V[vec * PP + quad * 4]);
            cur.x += v4.x; cur.y += v4.y; cur.z += v4.z; cur.w += v4.w;
            *reinterpret_cast<float4*>(&g_V[vec * PP + quad * 4]) = cur;
        }
    }
}

extern "C" void kernel_launch(void* const* d_in, const int* in_sizes, int n_in,
                              void* d_out, int out_size)
{
    const float* x = (const float*)d_in[0];
    const float* W = (const float*)d_in[1];
    if (n_in >= 2 && in_sizes[0] > in_sizes[1]) {
        const float* tmp = x; x = W; W = tmp;
    }
    float* out = (float*)d_out;

    cudaFuncSetAttribute(caps_pass0_mma,
        cudaFuncAttributeMaxDynamicSharedMemorySize, SMEM0_B);
    cudaFuncSetAttribute(caps_pass1,
        cudaFuncAttributeMaxDynamicSharedMemorySize, SMEM1_B);

    const int GRID1 = NBT1 * NNT1;                          // 256
    const int SQ_BLOCK = 256;
    const int SQ_GRID  = (BB * JJ * 32 + SQ_BLOCK - 1) / SQ_BLOCK;  // 512

    caps_dummy<<<1, 32>>>();                                // 1 (slot 6 = pass1 #2)
    caps_pass0_mma<<<128, 256, SMEM0_B>>>(x, W);            // 2
    caps_squash<<<SQ_GRID, SQ_BLOCK>>>(out, 0, NNT0);       // 3: V = v0
    caps_pass1<<<GRID1, TPB, SMEM1_B>>>(x, W);              // 4
    caps_squash<<<SQ_GRID, SQ_BLOCK>>>(out, 1, NNT1);       // 5: V += v1
    caps_pass1<<<GRID1, TPB, SMEM1_B>>>(x, W);              // 6 <- profiled
    caps_squash<<<SQ_GRID, SQ_BLOCK>>>(out, 2, NNT1);       // 7: out
}

// round 17
// speedup vs baseline: 1.6102x; 1.0171x over previous
#include <cuda_runtime.h>
#include <cstdint>

// Capsule routing. x:[128,2048,8] W:[32,2048,16,8] out:[128,32,16]
// R17 = R16 champion (pass0 mma.sync tf32 GEMM + lane=j warp-softmax routed
// pass) with: alignment dummy removed and pass1 staging 2 n per pipeline
// stage (barriers per kernel 64 -> 32). b_k = (sum_{i<k} v_i) . u_hat.

#define BB 128
#define NN 2048
#define DD 8
#define JJ 32
#define PP 16
#define TPB 128
#define BT1  16
#define NC1  64
#define NBT1 8
#define NNT1 32
#define NNT0 64
#define WJS  132
#define WBUF (JJ * WJS)                 // 4224 floats per n
#define XOFF (4 * WBUF)                 // 2 stages x 2 n
#define X1F  (NC1 * BT1 * DD)           // 8192
#define SMEM1_B ((XOFF + X1F) * 4)      // 100352 B

// pass0 mma smem: rows padded to 44 floats (176B): conflict-free frag loads
#define RS    44
#define AS_F  (128 * RS)
#define BS_F  (256 * RS)
#define BUF_F (AS_F + BS_F)
#define SMEM0_B (2 * BUF_F * 4)         // 135168 B

typedef unsigned long long u64;

__device__ __forceinline__ u64 fma2(u64 a, u64 b, u64 c) {
    u64 d; asm("fma.rn.f32x2 %0, %1, %2, %3;" : "=l"(d) : "l"(a), "l"(b), "l"(c));
    return d;
}
__device__ __forceinline__ u64 mul2(u64 a, u64 b) {
    u64 d; asm("mul.rn.f32x2 %0, %1, %2;" : "=l"(d) : "l"(a), "l"(b));
    return d;
}
__device__ __forceinline__ float lohi_add(u64 v) {
    float a, b; asm("mov.b64 {%0, %1}, %2;" : "=f"(a), "=f"(b) : "l"(v));
    return a + b;
}
__device__ __forceinline__ unsigned smem_u32(const void* p) {
    return (unsigned)__cvta_generic_to_shared(p);
}
__device__ __forceinline__ void cp16(unsigned dst, const void* src) {
    asm volatile("cp.async.cg.shared.global [%0], [%1], 16;" :: "r"(dst), "l"(src));
}
__device__ __forceinline__ void cp_commit() { asm volatile("cp.async.commit_group;"); }
__device__ __forceinline__ void cp_wait0()  { asm volatile("cp.async.wait_group 0;"); }
__device__ __forceinline__ uint32_t tf32(float v) {
    uint32_t t; asm("cvt.rna.tf32.f32 %0, %1;" : "=r"(t) : "f"(v));
    return t;
}
__device__ __forceinline__ void mma8(float* c, const uint32_t* a, const uint32_t* b) {
    asm volatile(
        "mma.sync.aligned.m16n8k8.row.col.f32.tf32.tf32.f32 "
        "{%0,%1,%2,%3}, {%4,%5,%6,%7}, {%8,%9}, {%0,%1,%2,%3};"
        : "+f"(c[0]), "+f"(c[1]), "+f"(c[2]), "+f"(c[3])
        : "r"(a[0]), "r"(a[1]), "r"(a[2]), "r"(a[3]), "r"(b[0]), "r"(b[1]));
}

__device__ __align__(16) float g_part[(size_t)NNT0 * BB * JJ * PP];  // 16MB
__device__ __align__(16) float g_V[BB * JJ * PP];

// ============ pass0: mma.sync tf32 GEMM (R11/R13 verified) ============
__global__ void __launch_bounds__(256, 1)
caps_pass0_mma(const float* __restrict__ xg, const float* __restrict__ Wg)
{
    extern __shared__ __align__(16) float sm[];
    const unsigned sm0 = smem_u32(sm);

    const int tid = threadIdx.x;
    const int w   = tid >> 5;
    const int lane = tid & 31;
    const int g   = lane >> 2;
    const int tig = lane & 3;
    const int jh  = blockIdx.x & 1;
    const int kt  = blockIdx.x >> 1;
    const int koff0 = kt * 256;

    auto stage = [&](int st) {
        const unsigned bufA = sm0 + (unsigned)((st & 1) * BUF_F) * 4;
        const unsigned bufB = bufA + (unsigned)AS_F * 4;
        const int koff = koff0 + st * 32;
        #pragma unroll
        for (int q = 0; q < 4; q++) {
            int c = tid + q * 256, b = c >> 3, h = c & 7;
            cp16(bufA + (unsigned)(b * RS + h * 4) * 4,
                 xg + (size_t)b * (NN * DD) + koff + h * 4);
        }
        #pragma unroll
        for (int q = 0; q < 8; q++) {
            int c = tid + q * 256, r = c >> 3, h = c & 7;
            int j = jh * 16 + (r >> 4), p = r & 15;
            int n = (koff >> 3) + (h >> 1);
            cp16(bufB + (unsigned)(r * RS + h * 4) * 4,
                 Wg + ((size_t)j * NN + n) * 128 + p * 8 + (h & 1) * 4);
        }
        cp_commit();
    };

    stage(0);

    float C[8][4][4];
    #pragma unroll
    for (int mt = 0; mt < 8; mt++)
        #pragma unroll
        for (int q = 0; q < 4; q++)
            #pragma unroll
            for (int e = 0; e < 4; e++) C[mt][q][e] = 0.0f;

    for (int st = 0; st < 8; st++) {
        cp_wait0();
        __syncthreads();
        if (st + 1 < 8) stage(st + 1);

        const float* As = sm + (st & 1) * BUF_F;
        const float* Bs = As + AS_F;

        #pragma unroll
        for (int kc = 0; kc < 4; kc++) {
            const int k0 = kc * 8 + tig;
            uint32_t Bf[4][2];
            #pragma unroll
            for (int q = 0; q < 4; q++) {
                const float* br = Bs + (w * 32 + q * 8 + g) * RS;
                Bf[q][0] = tf32(br[k0]);
                Bf[q][1] = tf32(br[k0 + 4]);
            }
            #pragma unroll
            for (int mt = 0; mt < 8; mt++) {
                const float* ar0 = As + (mt * 16 + g) * RS;
                const float* ar1 = ar0 + 8 * RS;
                uint32_t Af[4];
                Af[0] = tf32(ar0[k0]);
                Af[1] = tf32(ar1[k0]);
                Af[2] = tf32(ar0[k0 + 4]);
                Af[3] = tf32(ar1[k0 + 4]);
                #pragma unroll
                for (int q = 0; q < 4; q++) mma8(C[mt][q], Af, Bf[q]);
            }
        }
    }

    const float inv = 1.0f / 32.0f;
    #pragma unroll
    for (int mt = 0; mt < 8; mt++) {
        #pragma unroll
        for (int q = 0; q < 4; q++) {
            int jpg = jh * 256 + w * 32 + q * 8 + tig * 2;
            int j = jpg >> 4, p = jpg & 15;
            int b0 = mt * 16 + g;
            float* d0 = &g_part[(((size_t)kt * BB + b0) * JJ + j) * PP + p];
            float* d1 = &g_part[(((size_t)kt * BB + b0 + 8) * JJ + j) * PP + p];
            *reinterpret_cast<float2*>(d0) =
                make_float2(C[mt][q][0] * inv, C[mt][q][1] * inv);
            *reinterpret_cast<float2*>(d1) =
                make_float2(C[mt][q][2] * inv, C[mt][q][3] * inv);
        }
    }
}

// ============ pass1: SIMT routed pass, lane = j, 2 n per stage ============
// Warp w owns b = b0 + w*4 + r (r=0..3); lane = j. One barrier per 2 n.
__global__ void __launch_bounds__(TPB, 2)
caps_pass1(const float* __restrict__ xg, const float* __restrict__ Wg)
{
    extern __shared__ __align__(16) float sm[];
    const unsigned sm0 = smem_u32(sm);

    const int tid  = threadIdx.x;
    const int lane = tid & 31;          // = j
    const int w    = tid >> 5;          // warp: 4 b's
    const int j    = lane;
    const int bt   = blockIdx.x & (NBT1 - 1);
    const int nt   = blockIdx.x >> 3;
    const int b0   = bt * BT1;
    const int n0   = nt * NC1;

    // V[b][j][:] for the warp's 4 b's, packed p-pairs
    u64 V2[4][8];
    #pragma unroll
    for (int r = 0; r < 4; r++) {
        const ulonglong2* vp = reinterpret_cast<const ulonglong2*>(
            &g_V[((size_t)(b0 + w * 4 + r) * JJ + j) * PP]);
        #pragma unroll
        for (int q = 0; q < 4; q++) {
            ulonglong2 t = vp[q]; V2[r][2*q] = t.x; V2[r][2*q+1] = t.y;
        }
    }

    const int jb = tid >> 5, cc = tid & 31;
    const float* wbase = Wg + (size_t)jb * NN * 128 + cc * 4;
    const unsigned wdst0 = sm0 + (unsigned)(jb * WJS + cc * 4) * 4;

    // stage s = n-pair (n0+2s, n0+2s+1) into buffer s&1
    auto stageW = [&](int s) {
        const unsigned base = wdst0 + (unsigned)((s & 1) * 2 * WBUF) * 4;
        #pragma unroll
        for (int t = 0; t < 2; t++) {
            const float* src = wbase + (size_t)(n0 + 2 * s + t) * 128;
            unsigned d = base + (unsigned)(t * WBUF) * 4;
            #pragma unroll
            for (int q = 0; q < 8; q++)
                cp16(d + q * (4 * WJS * 4), src + (size_t)q * 4 * NN * 128);
        }
        cp_commit();
    };

    // prologue: x preload (all 64 n) + W stage 0, one group
    #pragma unroll
    for (int q = 0; q < 16; q++) {
        int c = tid + q * TPB;
        int n = c >> 5, b = (c >> 1) & 15, h = c & 1;
        cp16(sm0 + (unsigned)(XOFF + n * (BT1*DD) + b * DD + h * 4) * 4,
             xg + ((size_t)(b0 + b) * NN + (n0 + n)) * DD + h * 4);
    }
    stageW(0);

    u64 s2[4][8];
    #pragma unroll
    for (int r = 0; r < 4; r++)
        #pragma unroll
        for (int q = 0; q < 8; q++) s2[r][q] = 0ull;

    // one full n of compute against W at sm-offset woff
    auto computeN = [&](int nn, int woff) {
        const float* xrow = sm + XOFF + nn * (BT1*DD);
        u64 X[4][4];
        #pragma unroll
        for (int r = 0; r < 4; r++) {
            const ulonglong2* xp =
                reinterpret_cast<const ulonglong2*>(xrow + (w * 4 + r) * DD);
            ulonglong2 t0 = xp[0], t1 = xp[1];
            X[r][0] = t0.x; X[r][1] = t0.y; X[r][2] = t1.x; X[r][3] = t1.y;
        }

        const float* Wj = sm + woff + j * WJS;
        u64 u2[4][8];
        #pragma unroll
        for (int p2 = 0; p2 < 8; p2++) {
            const ulonglong2* wr = reinterpret_cast<const ulonglong2*>(Wj + p2 * 16);
            ulonglong2 w0 = wr[0], w1 = wr[1], w2 = wr[2], w3 = wr[3];
            #pragma unroll
            for (int r = 0; r < 4; r++) {
                u64 a = mul2(w0.x, X[r][0]);
                a = fma2(w0.y, X[r][1], a);
                a = fma2(w1.x, X[r][2], a);
                a = fma2(w1.y, X[r][3], a);
                u64 b = mul2(w2.x, X[r][0]);
                b = fma2(w2.y, X[r][1], b);
                b = fma2(w3.x, X[r][2], b);
                b = fma2(w3.y, X[r][3], b);
                u64 pr; asm("mov.b64 %0, {%1, %2};" : "=l"(pr)
                            : "f"(lohi_add(a)), "f"(lohi_add(b)));
                u2[r][p2] = pr;
            }
        }

        float e[4];
        #pragma unroll
        for (int r = 0; r < 4; r++) {
            u64 la = mul2(V2[r][0], u2[r][0]);
            u64 lb = mul2(V2[r][1], u2[r][1]);
            la = fma2(V2[r][2], u2[r][2], la);
            lb = fma2(V2[r][3], u2[r][3], lb);
            la = fma2(V2[r][4], u2[r][4], la);
            lb = fma2(V2[r][5], u2[r][5], lb);
            la = fma2(V2[r][6], u2[r][6], la);
            lb = fma2(V2[r][7], u2[r][7], lb);
            e[r] = __expf(lohi_add(la) + lohi_add(lb));   // |logit| small
        }

        float sum[4];
        #pragma unroll
        for (int r = 0; r < 4; r++) sum[r] = e[r];
        #pragma unroll
        for (int m = 1; m < 32; m <<= 1) {
            #pragma unroll
            for (int r = 0; r < 4; r++)
                sum[r] += __shfl_xor_sync(0xffffffffu, sum[r], m);
        }

        #pragma unroll
        for (int r = 0; r < 4; r++) {
            float c = e[r] * __frcp_rn(sum[r]);
            u64 c2; asm("mov.b64 %0, {%1, %1};" : "=l"(c2) : "f"(c));
            #pragma unroll
            for (int q = 0; q < 8; q++) s2[r][q] = fma2(c2, u2[r][q], s2[r][q]);
        }
    };

    // distance-1 double buffer over 32 n-pair stages; 1 barrier per 2 n
    for (int s = 0; s < NC1 / 2; s++) {
        cp_wait0();
        __syncthreads();
        if (s + 1 < NC1 / 2) stageW(s + 1);
        const int woff = (s & 1) * 2 * WBUF;
        computeN(2 * s,     woff);
        computeN(2 * s + 1, woff + WBUF);
    }

    // epilogue: coalesced (j = lane -> consecutive 64B rows)
    #pragma unroll
    for (int r = 0; r < 4; r++) {
        ulonglong2* dst = reinterpret_cast<ulonglong2*>(
            &g_part[(((size_t)nt * BB + b0 + w * 4 + r) * JJ + j) * PP]);
        #pragma unroll
        for (int q = 0; q < 4; q++) {
            ulonglong2 t; t.x = s2[r][2*q]; t.y = s2[r][2*q+1]; dst[q] = t;
        }
    }
}

// ============ reduce over nt (k-split 8 + shfl), squash, update V / out ====
__global__ void caps_squash(float* __restrict__ outg, int stage, int nnt)
{
    int t    = blockIdx.x * blockDim.x + threadIdx.x;
    int quad = t & 3;
    int k    = (t >> 2) & 7;
    int vec  = t >> 5;
    if (vec >= BB * JJ) return;

    float4 acc = make_float4(0.f, 0.f, 0.f, 0.f);
    int cnt = nnt >> 3;
    for (int ntk = 0; ntk < cnt; ntk++) {
        int nt = k * cnt + ntk;
        float4 v = *reinterpret_cast<const float4*>(
            &g_part[((size_t)nt * BB * JJ + vec) * PP + quad * 4]);
        acc.x += v.x; acc.y += v.y; acc.z += v.z; acc.w += v.w;
    }
    #pragma unroll
    for (int m = 4; m <= 16; m <<= 1) {
        acc.x += __shfl_xor_sync(0xffffffffu, acc.x, m);
        acc.y += __shfl_xor_sync(0xffffffffu, acc.y, m);
        acc.z += __shfl_xor_sync(0xffffffffu, acc.z, m);
        acc.w += __shfl_xor_sync(0xffffffffu, acc.w, m);
    }

    float s2 = acc.x * acc.x + acc.y * acc.y + acc.z * acc.z + acc.w * acc.w;
    s2 += __shfl_xor_sync(0xffffffffu, s2, 1);
    s2 += __shfl_xor_sync(0xffffffffu, s2, 2);

    float scale = s2 / ((1.0f + s2) * sqrtf(s2 + 1e-7f));
    float4 v4 = make_float4(acc.x * scale, acc.y * scale,
                            acc.z * scale, acc.w * scale);

    if (k == 0) {
        if (stage == 2) {
            *reinterpret_cast<float4*>(&outg[vec * PP + quad * 4]) = v4;
        } else if (stage == 0) {
            *reinterpret_cast<float4*>(&g_V[vec * PP + quad * 4]) = v4;
        } else {
            float4 cur = *reinterpret_cast<const float4*>(&g_V[vec * PP + quad * 4]);
            cur.x += v4.x; cur.y += v4.y; cur.z += v4.z; cur.w += v4.w;
            *reinterpret_cast<float4*>(&g_V[vec * PP + quad * 4]) = cur;
        }
    }
}

extern "C" void kernel_launch(void* const* d_in, const int* in_sizes, int n_in,
                              void* d_out, int out_size)
{
    const float* x = (const float*)d_in[0];
    const float* W = (const float*)d_in[1];
    if (n_in >= 2 && in_sizes[0] > in_sizes[1]) {
        const float* tmp = x; x = W; W = tmp;
    }
    float* out = (float*)d_out;

    cudaFuncSetAttribute(caps_pass0_mma,
        cudaFuncAttributeMaxDynamicSharedMemorySize, SMEM0_B);
    cudaFuncSetAttribute(caps_pass1,
        cudaFuncAttributeMaxDynamicSharedMemorySize, SMEM1_B);

    const int GRID1 = NBT1 * NNT1;                          // 256
    const int SQ_BLOCK = 256;
    const int SQ_GRID  = (BB * JJ * 32 + SQ_BLOCK - 1) / SQ_BLOCK;  // 512

    caps_pass0_mma<<<128, 256, SMEM0_B>>>(x, W);
    caps_squash<<<SQ_GRID, SQ_BLOCK>>>(out, 0, NNT0);       // V = v0
    caps_pass1<<<GRID1, TPB, SMEM1_B>>>(x, W);
    caps_squash<<<SQ_GRID, SQ_BLOCK>>>(out, 1, NNT1);       // V += v1
    caps_pass1<<<GRID1, TPB, SMEM1_B>>>(x, W);
    caps_squash<<<SQ_GRID, SQ_BLOCK>>>(out, 2, NNT1);       // out
}